// round 3
// baseline (speedup 1.0000x reference)
#include <cuda_runtime.h>

#define Bb 16
#define Dd 128
#define Hh 128
#define Ww 128
#define HW 16384
#define Cc 6
#define OH 512
#define OW 512
#define INV12 (1.0f/12.0f)
#define TILE 512

__device__ float g_sums[Bb*Cc*Dd];
__device__ int   g_counts[Bb*Cc];
__device__ float g_x[Bb*Cc*HW];
__device__ int   g_lo[OW];
__device__ float g_w[OW];

// ---------------------------------------------------------------- init:
// zero sums/counts + bilinear coord table (fp64 once, matches numpy)
__global__ void kInit() {
    int i = blockIdx.x * 256 + threadIdx.x;
    if (i < Bb*Cc*Dd) g_sums[i] = 0.f;
    if (i < Bb*Cc)    g_counts[i] = 0;
    if (i < OW) {
        double s = (double)i * (double)(Ww - 1) / (double)(OW - 1);
        int l = (int)s; if (l > Ww - 2) l = Ww - 2;
        g_lo[i] = l;
        g_w[i]  = (float)(s - (double)l);
    }
}

// ---------------------------------------------------------------- fused pass:
// pass1: per-pixel class dot, argmax -> smem mask, counts, x = dot/12 + b
// pass2: re-read own tile (L2-resident via occupancy cap) -> masked sums
__global__ void __launch_bounds__(256, 2)
kAB(const float* __restrict__ assp,
    const float* __restrict__ cls_w,
    const float* __restrict__ cls_b) {
    __shared__ float sW[Cc*Dd];
    __shared__ float sB[Cc];
    __shared__ int   sh[Cc];
    __shared__ unsigned char smask[TILE];
    __shared__ float bins[8][32][9];

    int t = threadIdx.x, w = t >> 5, lane = t & 31;
    for (int i = t; i < Cc*Dd; i += 256) sW[i] = cls_w[i];
    if (t < Cc) { sB[t] = cls_b[t]; sh[t] = 0; }
    __syncthreads();

    int b     = blockIdx.y;
    int tbase = blockIdx.x * TILE;
    const float* src = assp + (size_t)b * Dd * HW + tbase;

    // ---- pass 1: 2 pixels / thread
    const float* p1 = src + 2 * t;
    float a0[Cc], a1[Cc];
#pragma unroll
    for (int c = 0; c < Cc; c++) { a0[c] = 0.f; a1[c] = 0.f; }

#pragma unroll 8
    for (int d = 0; d < Dd; d++) {
        float2 f = *(const float2*)(p1 + (size_t)d * HW);
#pragma unroll
        for (int c = 0; c < Cc; c++) {
            float wv = sW[c*Dd + d];
            a0[c] = fmaf(f.x, wv, a0[c]);
            a1[c] = fmaf(f.y, wv, a1[c]);
        }
    }

    int m0 = 0, m1 = 0; float b0 = a0[0], b1 = a1[0];
#pragma unroll
    for (int c = 1; c < Cc; c++) {
        if (a0[c] > b0) { b0 = a0[c]; m0 = c; }
        if (a1[c] > b1) { b1 = a1[c]; m1 = c; }
    }
    smask[2*t]     = (unsigned char)m0;
    smask[2*t + 1] = (unsigned char)m1;

#pragma unroll
    for (int c = 0; c < Cc; c++) {
        float2 xv;
        xv.x = a0[c] * INV12 + sB[c];
        xv.y = a1[c] * INV12 + sB[c];
        *(float2*)(g_x + ((size_t)(b*Cc + c))*HW + tbase + 2*t) = xv;
    }

    atomicAdd(&sh[m0], 1);
    atomicAdd(&sh[m1], 1);
    __syncthreads();                       // also publishes smask for pass 2
    if (t < Cc) atomicAdd(&g_counts[b*Cc + t], sh[t]);

    // ---- pass 2: warp w handles d = w, w+8, ..., per-lane padded bins
    float* myb = bins[w][lane];
    const uchar4* sm4 = (const uchar4*)smask;

#pragma unroll 2
    for (int i = 0; i < 16; i++) {
        int d = w + i * 8;
        const float4* s4 = (const float4*)(src + (size_t)d * HW);
#pragma unroll
        for (int c = 0; c < Cc; c++) myb[c] = 0.f;
#pragma unroll
        for (int k = 0; k < TILE/128; k++) {
            float4 v  = s4[lane + k*32];
            uchar4 m4 = sm4[lane + k*32];
            myb[m4.x] += v.x;
            myb[m4.y] += v.y;
            myb[m4.z] += v.z;
            myb[m4.w] += v.w;
        }
        __syncwarp();
#pragma unroll
        for (int c = 0; c < Cc; c++) {
            float val = myb[c];
#pragma unroll
            for (int off = 16; off; off >>= 1)
                val += __shfl_down_sync(0xffffffffu, val, off);
            if (lane == 0) atomicAdd(&g_sums[(b*Cc + c)*Dd + d], val);
        }
        __syncwarp();
    }
}

// ---------------------------------------------------------------- drop patch
// (protoC folded inline: proto = cnt>0 ? sums/(cnt+1e-5) : 0)
__global__ void kC1(const float* __restrict__ assp,
                    const float* __restrict__ cls_w,
                    const float* __restrict__ cls_b,
                    const int* __restrict__ px,
                    const int* __restrict__ py) {
    int b = blockIdx.y, p = blockIdx.x, t = threadIdx.x;  // blockDim = 128 (= d)
    int pix = px[p] * Ww + py[p];

    __shared__ float scnt[Cc];
    __shared__ float sacc[Cc];
    __shared__ int   scstar;

    if (t < Cc) {
        scnt[t] = (float)g_counts[b*Cc + t];
        sacc[t] = 0.f;
    }
    __syncthreads();

    float pr[Cc];
#pragma unroll
    for (int c = 0; c < Cc; c++) {
        float cf = scnt[c];
        pr[c] = (cf > 0.f) ? g_sums[(b*Cc + c)*Dd + t] / (cf + 1e-5f) : 0.f;
    }

    float f = assp[((size_t)(b*Dd + t)) * HW + pix];
#pragma unroll
    for (int c = 0; c < Cc; c++) {
        float dd = f - pr[c];
        atomicAdd(&sacc[c], dd * dd);
    }
    __syncthreads();
    if (t == 0) {
        int cs = 0; float bd = sqrtf(sacc[0]);
#pragma unroll
        for (int c = 1; c < Cc; c++) {
            float dv = sqrtf(sacc[c]);
            if (dv < bd) { bd = dv; cs = c; }
        }
        scstar = cs;
    }
    __syncthreads();
    int cs = scstar;
    float cf = scnt[cs];
    float g  = (cf > 0.f) ? g_sums[(b*Cc + cs)*Dd + t] / (cf + 1e-5f) : 0.f;
    if (t < Cc) sacc[t] = 0.f;
    __syncthreads();
#pragma unroll
    for (int c = 0; c < Cc; c++)
        atomicAdd(&sacc[c], g * cls_w[c*Dd + t]);
    __syncthreads();
    if (t < Cc)
        g_x[((size_t)(b*Cc + t)) * HW + pix] = sacc[t] * INV12 + cls_b[t];
}

// ---------------------------------------------------------------- bilinear 4x up
// 4 output rows per block, table-driven, no fp64
__global__ void kD(float* __restrict__ out) {
    __shared__ int   slx[OW];
    __shared__ float swx[OW];
    int t = threadIdx.x;
    for (int j = t; j < OW; j += 256) {
        slx[j] = g_lo[j];
        swx[j] = g_w[j];
    }
    __syncthreads();

    int b = blockIdx.z, c = blockIdx.y;
    int I  = blockIdx.x * 4 + (t >> 6);
    int J0 = (t & 63) * 8;

    int   ly = slx[I];
    float wy = swx[I];

    const float* xp = g_x + ((size_t)(b*Cc + c)) * HW;
    const float* r0 = xp + ly * Ww;
    const float* r1 = r0 + Ww;

    float res[8];
#pragma unroll
    for (int j = 0; j < 8; j++) {
        int   J  = J0 + j;
        int   lx = slx[J];
        float wx = swx[J];
        float v00 = r0[lx], v01 = r0[lx+1], v10 = r1[lx], v11 = r1[lx+1];
        float top = v00 + wx * (v01 - v00);
        float bot = v10 + wx * (v11 - v10);
        res[j] = top + wy * (bot - top);
    }
    float* o = out + (((size_t)(b*Cc + c)) * OH + I) * OW + J0;
    *(float4*)o       = *(float4*)res;
    *(float4*)(o + 4) = *(float4*)(res + 4);
}

// ----------------------------------------------------------------
extern "C" void kernel_launch(void* const* d_in, const int* in_sizes, int n_in,
                              void* d_out, int out_size) {
    const float* assp  = (const float*)d_in[0];
    const float* cls_w = (const float*)d_in[1];
    const float* cls_b = (const float*)d_in[2];
    const int*   px    = (const int*)d_in[7];
    const int*   py    = (const int*)d_in[8];
    float* out = (float*)d_out;
    int P = in_sizes[7];

    kInit<<<48, 256>>>();
    kAB<<<dim3(HW/TILE, Bb), 256>>>(assp, cls_w, cls_b);
    kC1<<<dim3(P, Bb), 128>>>(assp, cls_w, cls_b, px, py);
    kD<<<dim3(OH/4, Cc, Bb), 256>>>(out);
}